// round 5
// baseline (speedup 1.0000x reference)
#include <cuda_runtime.h>
#include <cuda_bf16.h>
#include <float.h>
#include <math.h>
#include <cstdint>

#define BB  8
#define NN  2048
#define KNN 20

// ---------------- scratch (device globals; no allocations) ----------------
__device__ float g_xx[BB * NN];
__device__ int   g_idx[BB * NN * KNN];
__device__ float g_y[(size_t)BB * NN * 256];
__device__ float g_c[(size_t)BB * NN * 256];
__device__ float g_hcat[(size_t)BB * NN * 512];
__device__ float g_tmp[(size_t)BB * NN * 1024];
__device__ __nv_bfloat16 g_a3[(size_t)BB * NN * 1536];   // split-bf16 A (h|l|h)
__device__ __nv_bfloat16 g_b3[(size_t)BB * NN * 384];    // split-bf16 B (h|h|l) pairwise
__device__ __nv_bfloat16 g_bf3[1024 * 1536];             // split-bf16 Wf
__device__ __nv_bfloat16 g_w3[256 * 384];                // split-bf16 layer W slice

// =================== split-precision conversion kernels ===================
__global__ void convA_kernel(const float* __restrict__ in, int ld, int C,
                             __nv_bfloat16* __restrict__ out, int K3) {
    int r = blockIdx.y;
    int c = blockIdx.x * 256 + threadIdx.x;
    if (c >= K3) return;
    size_t ro = (size_t)r * K3;
    if (c < C) {
        float xv = in[(size_t)r * ld + c];
        __nv_bfloat16 h = __float2bfloat16(xv);
        __nv_bfloat16 l = __float2bfloat16(xv - __bfloat162float(h));
        out[ro + c] = h; out[ro + C + c] = l; out[ro + 2 * C + c] = h;
    } else if (c >= 3 * C) {
        out[ro + c] = __float2bfloat16(0.f);
    }
}
__global__ void convB_kernel(const float* __restrict__ in, int ld, int C,
                             __nv_bfloat16* __restrict__ out, int K3) {
    int r = blockIdx.y;
    int c = blockIdx.x * 256 + threadIdx.x;
    if (c >= K3) return;
    size_t ro = (size_t)r * K3;
    if (c < C) {
        float xv = in[(size_t)r * ld + c];
        __nv_bfloat16 h = __float2bfloat16(xv);
        __nv_bfloat16 l = __float2bfloat16(xv - __bfloat162float(h));
        out[ro + c] = h; out[ro + C + c] = h; out[ro + 2 * C + c] = l;
    } else if (c >= 3 * C) {
        out[ro + c] = __float2bfloat16(0.f);
    }
}

#define LDP 72   // padded k-stride (bf16 elems) -> conflict-free frags

__device__ __forceinline__ void mma16816(float* d, const uint32_t* a, const uint32_t* b) {
    asm volatile(
        "mma.sync.aligned.m16n8k16.row.col.f32.bf16.bf16.f32 "
        "{%0,%1,%2,%3}, {%4,%5,%6,%7}, {%8,%9}, {%0,%1,%2,%3};"
        : "+f"(d[0]), "+f"(d[1]), "+f"(d[2]), "+f"(d[3])
        : "r"(a[0]), "r"(a[1]), "r"(a[2]), "r"(a[3]), "r"(b[0]), "r"(b[1]));
}

// =================== mma.sync bf16 GEMM, 128x128 block tile ===================
// out = A3 · B3^T, fp32 accum.  8 warps, 32x64 warp tile, m16n8k16 MMAs.
// out[m][o] = (acc + bias[o]) [leaky if act]
__global__ void __launch_bounds__(256)
mma_gemm(const __nv_bfloat16* __restrict__ A3, int lda3,
         const __nv_bfloat16* __restrict__ B3, int ldb3,
         int Nvalid, int K3,
         float* __restrict__ out, int ldo,
         const float* __restrict__ bias, int act) {
    __shared__ __nv_bfloat16 As[128][LDP];
    __shared__ __nv_bfloat16 Bs[128][LDP];

    int tid = threadIdx.x;
    int wid = tid >> 5, lane = tid & 31;
    int wr = wid & 3, wc = wid >> 2;
    int gr = lane >> 2, tg = lane & 3;

    int m0 = blockIdx.y * 128, o0 = blockIdx.x * 128;

    float acc[2][8][4] = {};

    for (int k0 = 0; k0 < K3; k0 += 64) {
#pragma unroll
        for (int i = 0; i < 4; ++i) {
            int e = tid + i * 256;
            int row = e >> 3, seg = e & 7;
            uint4 va = *((const uint4*)(A3 + (size_t)(m0 + row) * lda3 + k0) + seg);
            *(uint4*)&As[row][seg * 8] = va;
            int brow = o0 + row;
            uint4 vb = make_uint4(0, 0, 0, 0);
            if (brow < Nvalid)
                vb = *((const uint4*)(B3 + (size_t)brow * ldb3 + k0) + seg);
            *(uint4*)&Bs[row][seg * 8] = vb;
        }
        __syncthreads();
#pragma unroll
        for (int kk = 0; kk < 64; kk += 16) {
            uint32_t af[2][4], bfr[8][2];
#pragma unroll
            for (int mi = 0; mi < 2; ++mi) {
                const __nv_bfloat16* pa = &As[wr * 32 + mi * 16 + gr][kk + tg * 2];
                af[mi][0] = *(const uint32_t*)pa;
                af[mi][1] = *(const uint32_t*)(pa + 8 * LDP);
                af[mi][2] = *(const uint32_t*)(pa + 8);
                af[mi][3] = *(const uint32_t*)(pa + 8 * LDP + 8);
            }
#pragma unroll
            for (int ni = 0; ni < 8; ++ni) {
                const __nv_bfloat16* pb = &Bs[wc * 64 + ni * 8 + gr][kk + tg * 2];
                bfr[ni][0] = *(const uint32_t*)pb;
                bfr[ni][1] = *(const uint32_t*)(pb + 8);
            }
#pragma unroll
            for (int mi = 0; mi < 2; ++mi)
#pragma unroll
                for (int ni = 0; ni < 8; ++ni)
                    mma16816(acc[mi][ni], af[mi], bfr[ni]);
        }
        __syncthreads();
    }

#pragma unroll
    for (int mi = 0; mi < 2; ++mi) {
        int mA = m0 + wr * 32 + mi * 16 + gr;
#pragma unroll
        for (int ni = 0; ni < 8; ++ni) {
            int o = o0 + wc * 64 + ni * 8 + tg * 2;
            if (o < Nvalid) {
                float u0 = acc[mi][ni][0], u1 = acc[mi][ni][1];
                float u2 = acc[mi][ni][2], u3 = acc[mi][ni][3];
                float b0 = bias ? bias[o] : 0.f, b1 = bias ? bias[o + 1] : 0.f;
                u0 += b0; u1 += b1; u2 += b0; u3 += b1;
                if (act) {
                    u0 = u0 > 0.f ? u0 : 0.2f * u0;
                    u1 = u1 > 0.f ? u1 : 0.2f * u1;
                    u2 = u2 > 0.f ? u2 : 0.2f * u2;
                    u3 = u3 > 0.f ? u3 : 0.2f * u3;
                }
                *(float2*)(out + (size_t)mA * ldo + o)       = make_float2(u0, u1);
                *(float2*)(out + (size_t)(mA + 8) * ldo + o) = make_float2(u2, u3);
            }
        }
    }
}

// =================== fused pairwise-distance + exact top-K ===================
// Block = 128 rows of one batch. Loops 16 col-tiles: mma -> smem stage ->
// per-row top-20 insertion lists (2 threads/row) -> final 2-way merge.
#define FUSE_SMEM (36864 + 67584 + 20480 + 20480)
__global__ void __launch_bounds__(256)
knn_fused(const __nv_bfloat16* __restrict__ A3, const __nv_bfloat16* __restrict__ B3,
          int K3, const float* __restrict__ xx, int* __restrict__ idxout) {
    extern __shared__ char dsm[];
    __nv_bfloat16 (*As)[LDP]  = (__nv_bfloat16(*)[LDP])dsm;
    __nv_bfloat16 (*Bs)[LDP]  = (__nv_bfloat16(*)[LDP])(dsm + 18432);
    float (*stage)[132]       = (float(*)[132])(dsm + 36864);
    float* hk = (float*)(dsm + 104448);    // 256 threads * 20 keys
    int*   hx = (int*)  (dsm + 124928);    // 256 threads * 20 idx

    int tid = threadIdx.x;
    int wid = tid >> 5, lane = tid & 31;
    int wr = wid & 3, wc = wid >> 2;
    int gr = lane >> 2, tg = lane & 3;

    int b  = blockIdx.y;
    int m0 = blockIdx.x * 128;
    const __nv_bfloat16* Ab = A3 + (size_t)b * NN * K3;
    const __nv_bfloat16* Bb = B3 + (size_t)b * NN * K3;
    const float* xxb = xx + (size_t)b * NN;

    // init private top-20 list (sorted ascending)
    int lbase = tid * 20;
#pragma unroll
    for (int j = 0; j < 20; ++j) { hk[lbase + j] = FLT_MAX; hx[lbase + j] = 0; }

    int srow = tid >> 1, shalf = tid & 1;

    for (int ct = 0; ct < 16; ++ct) {
        int c0 = ct * 128;
        float acc[2][8][4] = {};

        for (int k0 = 0; k0 < K3; k0 += 64) {
#pragma unroll
            for (int i = 0; i < 4; ++i) {
                int e = tid + i * 256;
                int row = e >> 3, seg = e & 7;
                uint4 va = *((const uint4*)(Ab + (size_t)(m0 + row) * K3 + k0) + seg);
                *(uint4*)&As[row][seg * 8] = va;
                uint4 vb = *((const uint4*)(Bb + (size_t)(c0 + row) * K3 + k0) + seg);
                *(uint4*)&Bs[row][seg * 8] = vb;
            }
            __syncthreads();
#pragma unroll
            for (int kk = 0; kk < 64; kk += 16) {
                uint32_t af[2][4], bfr[8][2];
#pragma unroll
                for (int mi = 0; mi < 2; ++mi) {
                    const __nv_bfloat16* pa = &As[wr * 32 + mi * 16 + gr][kk + tg * 2];
                    af[mi][0] = *(const uint32_t*)pa;
                    af[mi][1] = *(const uint32_t*)(pa + 8 * LDP);
                    af[mi][2] = *(const uint32_t*)(pa + 8);
                    af[mi][3] = *(const uint32_t*)(pa + 8 * LDP + 8);
                }
#pragma unroll
                for (int ni = 0; ni < 8; ++ni) {
                    const __nv_bfloat16* pb = &Bs[wc * 64 + ni * 8 + gr][kk + tg * 2];
                    bfr[ni][0] = *(const uint32_t*)pb;
                    bfr[ni][1] = *(const uint32_t*)(pb + 8);
                }
#pragma unroll
                for (int mi = 0; mi < 2; ++mi)
#pragma unroll
                    for (int ni = 0; ni < 8; ++ni)
                        mma16816(acc[mi][ni], af[mi], bfr[ni]);
            }
            __syncthreads();
        }

        // epilogue: d2 tile into smem stage
#pragma unroll
        for (int mi = 0; mi < 2; ++mi) {
            int lr = wr * 32 + mi * 16 + gr;
            float xrA = xxb[m0 + lr], xrB = xxb[m0 + lr + 8];
#pragma unroll
            for (int ni = 0; ni < 8; ++ni) {
                int lc = wc * 64 + ni * 8 + tg * 2;
                float xc0 = xxb[c0 + lc], xc1 = xxb[c0 + lc + 1];
                float u0 = xrA - 2.f * acc[mi][ni][0] + xc0;
                float u1 = xrA - 2.f * acc[mi][ni][1] + xc1;
                float u2 = xrB - 2.f * acc[mi][ni][2] + xc0;
                float u3 = xrB - 2.f * acc[mi][ni][3] + xc1;
                *(float2*)&stage[lr][lc]     = make_float2(u0, u1);
                *(float2*)&stage[lr + 8][lc] = make_float2(u2, u3);
            }
        }
        __syncthreads();

        // per-thread scan of 64 values (interleaved cols), exact insertion sort
        float worst = hk[lbase + 19];
#pragma unroll 4
        for (int v = 0; v < 64; ++v) {
            int lc = (v << 1) | shalf;
            float kv = stage[srow][lc];
            if (kv < worst) {
                int p = 19;
                while (p > 0 && kv < hk[lbase + p - 1]) {
                    hk[lbase + p] = hk[lbase + p - 1];
                    hx[lbase + p] = hx[lbase + p - 1];
                    --p;
                }
                hk[lbase + p] = kv;
                hx[lbase + p] = c0 + lc;
                worst = hk[lbase + 19];
            }
        }
        __syncthreads();
    }

    // merge two sorted 20-lists per row (tie -> lower index)
    if (tid < 128) {
        int b0 = (tid * 2) * 20, b1 = (tid * 2 + 1) * 20;
        int i0 = 0, i1 = 0;
        size_t obase = ((size_t)b * NN + m0 + tid) * KNN;
#pragma unroll
        for (int k = 0; k < KNN; ++k) {
            float k0 = hk[b0 + i0], k1 = hk[b1 + i1];
            int   x0 = hx[b0 + i0], x1 = hx[b1 + i1];
            bool take0 = (k0 < k1) || (k0 == k1 && x0 < x1);
            if (take0) { idxout[obase + k] = x0; ++i0; }
            else       { idxout[obase + k] = x1; ++i1; }
        }
    }
}

// =================== small kernels ===================
__global__ void xx_kernel(const float* __restrict__ X, int ldx, int C,
                          float* __restrict__ xx) {
    int i = blockIdx.x * blockDim.x + threadIdx.x;
    if (i >= BB * NN) return;
    const float* p = X + (size_t)i * ldx;
    float s = 0.f;
    for (int c = 0; c < C; ++c) { float v = p[c]; s += v * v; }
    xx[i] = s;
}

__global__ void edgemax(const float* __restrict__ y, const float* __restrict__ c,
                        const int* __restrict__ idx, float* __restrict__ out,
                        int O, int ldo) {
    __shared__ int sid[KNN];
    int b = blockIdx.y, n = blockIdx.x;
    int t = threadIdx.x;
    if (t < KNN) sid[t] = idx[((size_t)b * NN + n) * KNN + t];
    __syncthreads();
    size_t mbase = (size_t)b * NN;
    float yc = y[(mbase + n) * O + t];
    float cc = c[(mbase + n) * O + t];
    float m = -FLT_MAX;
#pragma unroll
    for (int k = 0; k < KNN; ++k) {
        float v = y[(mbase + sid[k]) * O + t] - yc + cc;
        v = v > 0.f ? v : 0.2f * v;
        m = fmaxf(m, v);
    }
    out[(mbase + n) * ldo + t] = m;
}

__global__ void maxpool(const float* __restrict__ tmp, float* __restrict__ out) {
    int b = blockIdx.y;
    int f = blockIdx.x * blockDim.x + threadIdx.x;
    const float* p = tmp + (size_t)b * NN * 1024 + f;
    float m = -FLT_MAX;
    for (int n = 0; n < NN; ++n) m = fmaxf(m, p[(size_t)n * 1024]);
    out[b * 1024 + f] = m;
}

// =================== launch ===================
extern "C" void kernel_launch(void* const* d_in, const int* in_sizes, int n_in,
                              void* d_out, int out_size) {
    const float* x     = (const float*)d_in[0];
    const float* Wl[4] = {(const float*)d_in[1], (const float*)d_in[3],
                          (const float*)d_in[5], (const float*)d_in[7]};
    const float* bl[4] = {(const float*)d_in[2], (const float*)d_in[4],
                          (const float*)d_in[6], (const float*)d_in[8]};
    const float* Wf = (const float*)d_in[9];
    const float* bf = (const float*)d_in[10];
    float* out = (float*)d_out;

    float *p_xx, *p_y, *p_c, *p_hcat, *p_tmp;
    __nv_bfloat16 *p_a3, *p_b3, *p_bf3, *p_w3;
    int* p_idx;
    cudaGetSymbolAddress((void**)&p_xx,   g_xx);
    cudaGetSymbolAddress((void**)&p_idx,  g_idx);
    cudaGetSymbolAddress((void**)&p_y,    g_y);
    cudaGetSymbolAddress((void**)&p_c,    g_c);
    cudaGetSymbolAddress((void**)&p_hcat, g_hcat);
    cudaGetSymbolAddress((void**)&p_tmp,  g_tmp);
    cudaGetSymbolAddress((void**)&p_a3,   g_a3);
    cudaGetSymbolAddress((void**)&p_b3,   g_b3);
    cudaGetSymbolAddress((void**)&p_bf3,  g_bf3);
    cudaGetSymbolAddress((void**)&p_w3,   g_w3);

    cudaFuncSetAttribute(knn_fused, cudaFuncAttributeMaxDynamicSharedMemorySize,
                         FUSE_SMEM);

    const int Cs[4]  = {3, 64, 64, 128};
    const int Os[4]  = {64, 64, 128, 256};
    const int off[4] = {0, 64, 128, 256};

    const float* Xin = x;
    int ldx = 3;
    for (int l = 0; l < 4; ++l) {
        int C = Cs[l], O = Os[l];
        int K3 = ((3 * C + 63) / 64) * 64;     // 64, 192, 192, 384

        xx_kernel<<<(BB * NN + 255) / 256, 256>>>(Xin, ldx, C, p_xx);
        convA_kernel<<<dim3((K3 + 255) / 256, BB * NN), 256>>>(Xin, ldx, C, p_a3, K3);
        convB_kernel<<<dim3((K3 + 255) / 256, BB * NN), 256>>>(Xin, ldx, C, p_b3, K3);
        // fused pairwise + top-k (no d2 matrix)
        knn_fused<<<dim3(16, BB), 256, FUSE_SMEM>>>(p_a3, p_b3, K3, p_xx, p_idx);
        // y = X * Wy^T
        convB_kernel<<<dim3((K3 + 255) / 256, O), 256>>>(Wl[l], 2 * C, C, p_w3, K3);
        mma_gemm<<<dim3((O + 127) / 128, (BB * NN) / 128), 256>>>(
            p_a3, K3, p_w3, K3, O, K3, p_y, O, nullptr, 0);
        // c = X * Wc^T + b
        convB_kernel<<<dim3((K3 + 255) / 256, O), 256>>>(Wl[l] + C, 2 * C, C, p_w3, K3);
        mma_gemm<<<dim3((O + 127) / 128, (BB * NN) / 128), 256>>>(
            p_a3, K3, p_w3, K3, O, K3, p_c, O, bl[l], 0);
        edgemax<<<dim3(NN, BB), O>>>(p_y, p_c, p_idx, p_hcat + off[l], O, 512);
        Xin = p_hcat + off[l];
        ldx = 512;
    }
    // final 512 -> 1024 linear + leaky, then max over N
    convA_kernel<<<dim3(1536 / 256, BB * NN), 256>>>(p_hcat, 512, 512, p_a3, 1536);
    convB_kernel<<<dim3(1536 / 256, 1024), 256>>>(Wf, 512, 512, p_bf3, 1536);
    mma_gemm<<<dim3(1024 / 128, (BB * NN) / 128), 256>>>(
        p_a3, 1536, p_bf3, 1536, 1024, 1536, p_tmp, 1024, bf, 1);
    maxpool<<<dim3(1024 / 256, BB), 256>>>(p_tmp, out);
}

// round 6
// speedup vs baseline: 2.0746x; 2.0746x over previous
#include <cuda_runtime.h>
#include <cuda_bf16.h>
#include <float.h>
#include <math.h>
#include <cstdint>

#define BB  8
#define NN  2048
#define KNN 20

// ---------------- scratch (device globals; no allocations) ----------------
__device__ __align__(16) float g_d2[(size_t)BB * NN * NN];
__device__ __align__(16) float g_xx[BB * NN];
__device__ __align__(16) int   g_idx[BB * NN * KNN];
__device__ __align__(16) float g_yc[(size_t)BB * NN * 512];    // y | c combined
__device__ __align__(16) float g_hcat[(size_t)BB * NN * 512];
__device__ __align__(16) float g_tmp[(size_t)BB * NN * 1024];
__device__ __align__(16) float g_bias2[512];
__device__ __align__(16) __nv_bfloat16 g_a3[(size_t)BB * NN * 1536];  // split A (h|l|h)
__device__ __align__(16) __nv_bfloat16 g_b3[(size_t)BB * NN * 384];   // split B (h|h|l)
__device__ __align__(16) __nv_bfloat16 g_bf3[1024 * 1536];            // split Wf
__device__ __align__(16) __nv_bfloat16 g_w3[512 * 384];               // split layer W (y|c)

// =================== split-precision conversion kernels ===================
__global__ void convA_kernel(const float* __restrict__ in, int ld, int C,
                             __nv_bfloat16* __restrict__ out, int K3) {
    int r = blockIdx.y;
    int c = blockIdx.x * 256 + threadIdx.x;
    if (c >= K3) return;
    size_t ro = (size_t)r * K3;
    if (c < C) {
        float xv = in[(size_t)r * ld + c];
        __nv_bfloat16 h = __float2bfloat16(xv);
        __nv_bfloat16 l = __float2bfloat16(xv - __bfloat162float(h));
        out[ro + c] = h; out[ro + C + c] = l; out[ro + 2 * C + c] = h;
    } else if (c >= 3 * C) {
        out[ro + c] = __float2bfloat16(0.f);
    }
}
__global__ void convB_kernel(const float* __restrict__ in, int ld, int C,
                             __nv_bfloat16* __restrict__ out, int K3) {
    int r = blockIdx.y;
    int c = blockIdx.x * 256 + threadIdx.x;
    if (c >= K3) return;
    size_t ro = (size_t)r * K3;
    if (c < C) {
        float xv = in[(size_t)r * ld + c];
        __nv_bfloat16 h = __float2bfloat16(xv);
        __nv_bfloat16 l = __float2bfloat16(xv - __bfloat162float(h));
        out[ro + c] = h; out[ro + C + c] = h; out[ro + 2 * C + c] = l;
    } else if (c >= 3 * C) {
        out[ro + c] = __float2bfloat16(0.f);
    }
}
__global__ void biascat(const float* __restrict__ bl, float* __restrict__ out, int O) {
    int i = threadIdx.x;
    if (i < O) out[i] = 0.f;
    else if (i < 2 * O) out[i] = bl[i - O];
}

#define LDP 72   // padded k-stride (bf16) -> conflict-free fragment loads

__device__ __forceinline__ void mma16816(float* d, const uint32_t* a, const uint32_t* b) {
    asm volatile(
        "mma.sync.aligned.m16n8k16.row.col.f32.bf16.bf16.f32 "
        "{%0,%1,%2,%3}, {%4,%5,%6,%7}, {%8,%9}, {%0,%1,%2,%3};"
        : "+f"(d[0]), "+f"(d[1]), "+f"(d[2]), "+f"(d[3])
        : "r"(a[0]), "r"(a[1]), "r"(a[2]), "r"(a[3]), "r"(b[0]), "r"(b[1]));
}
__device__ __forceinline__ uint32_t smem_u32(const void* p) {
    uint32_t a;
    asm("{ .reg .u64 t; cvta.to.shared.u64 t, %1; cvt.u32.u64 %0, t; }" : "=r"(a) : "l"(p));
    return a;
}
#define CPA(dst, src, n) \
    asm volatile("cp.async.cg.shared.global [%0], [%1], 16, %2;" \
                 :: "r"(dst), "l"(src), "r"(n))
#define CPA_COMMIT() asm volatile("cp.async.commit_group;" ::: "memory")
#define CPA_WAIT1()  asm volatile("cp.async.wait_group 1;" ::: "memory")
#define CPA_WAIT0()  asm volatile("cp.async.wait_group 0;" ::: "memory")

#define MMA_SMEM (2 * 2 * 128 * LDP * 2)   // 2 stages x (A,B) x 128xLDP bf16

// =================== cp.async-pipelined mma.sync GEMM, 128x128 tile ===============
// mode 0: out[m][o] = acc + bias[o]  (leaky if act)
// mode 1: out[m][o] = xx[m] - 2*acc + xx[o]
__global__ void __launch_bounds__(256)
mma_gemm(const __nv_bfloat16* __restrict__ A3, int lda3, size_t zsA,
         const __nv_bfloat16* __restrict__ B3, int ldb3, size_t zsB,
         int Nvalid, int K3,
         float* __restrict__ out, int ldo, size_t zsO,
         const float* __restrict__ bias, int act,
         int mode, const float* __restrict__ xx, int zsXX) {
    extern __shared__ __nv_bfloat16 sm[];
    int tid = threadIdx.x;
    int wid = tid >> 5, lane = tid & 31;
    int wr = wid & 3, wc = wid >> 2;
    int gr = lane >> 2, tg = lane & 3;

    int m0 = blockIdx.y * 128, o0 = blockIdx.x * 128;
    const __nv_bfloat16* Ab = A3 + blockIdx.z * zsA;
    const __nv_bfloat16* Bb = B3 + blockIdx.z * zsB;
    uint32_t sbase = smem_u32(sm);
    int nch = K3 / 64;

    // issue one 128x64 A-tile + B-tile into stage s via cp.async
    auto issue = [&](int s, int k0) {
#pragma unroll
        for (int i = 0; i < 4; ++i) {
            int e = tid + i * 256;
            int row = e >> 3, seg = e & 7;
            uint32_t da = sbase + (uint32_t)(s * 2 * 128 * LDP + row * LDP + seg * 8) * 2;
            CPA(da, Ab + (size_t)(m0 + row) * lda3 + k0 + seg * 8, 16);
            int brow = o0 + row;
            int srow = brow < Nvalid ? brow : (Nvalid - 1);
            uint32_t db = sbase + (uint32_t)((s * 2 + 1) * 128 * LDP + row * LDP + seg * 8) * 2;
            CPA(db, Bb + (size_t)srow * ldb3 + k0 + seg * 8, brow < Nvalid ? 16 : 0);
        }
        CPA_COMMIT();
    };

    float acc[2][8][4] = {};
    issue(0, 0);
    for (int ch = 0; ch < nch; ++ch) {
        if (ch + 1 < nch) { issue((ch + 1) & 1, (ch + 1) * 64); CPA_WAIT1(); }
        else              { CPA_WAIT0(); }
        __syncthreads();
        const __nv_bfloat16 (*As)[LDP] =
            (const __nv_bfloat16(*)[LDP])(sm + (ch & 1) * 2 * 128 * LDP);
        const __nv_bfloat16 (*Bs)[LDP] = As + 128;
#pragma unroll
        for (int kk = 0; kk < 64; kk += 16) {
            uint32_t af[2][4], bfr[8][2];
#pragma unroll
            for (int mi = 0; mi < 2; ++mi) {
                const __nv_bfloat16* pa = &As[wr * 32 + mi * 16 + gr][kk + tg * 2];
                af[mi][0] = *(const uint32_t*)pa;
                af[mi][1] = *(const uint32_t*)(pa + 8 * LDP);
                af[mi][2] = *(const uint32_t*)(pa + 8);
                af[mi][3] = *(const uint32_t*)(pa + 8 * LDP + 8);
            }
#pragma unroll
            for (int ni = 0; ni < 8; ++ni) {
                const __nv_bfloat16* pb = &Bs[wc * 64 + ni * 8 + gr][kk + tg * 2];
                bfr[ni][0] = *(const uint32_t*)pb;
                bfr[ni][1] = *(const uint32_t*)(pb + 8);
            }
#pragma unroll
            for (int mi = 0; mi < 2; ++mi)
#pragma unroll
                for (int ni = 0; ni < 8; ++ni)
                    mma16816(acc[mi][ni], af[mi], bfr[ni]);
        }
        __syncthreads();
    }

    float* outb = out + blockIdx.z * zsO;
    const float* xxb = (mode == 1) ? xx + (size_t)blockIdx.z * zsXX : nullptr;
#pragma unroll
    for (int mi = 0; mi < 2; ++mi) {
        int mA = m0 + wr * 32 + mi * 16 + gr;
        float xrA = 0.f, xrB = 0.f;
        if (mode == 1) { xrA = xxb[mA]; xrB = xxb[mA + 8]; }
#pragma unroll
        for (int ni = 0; ni < 8; ++ni) {
            int o = o0 + wc * 64 + ni * 8 + tg * 2;
            if (o < Nvalid) {
                float u0 = acc[mi][ni][0], u1 = acc[mi][ni][1];
                float u2 = acc[mi][ni][2], u3 = acc[mi][ni][3];
                if (mode == 0) {
                    float b0 = bias ? bias[o] : 0.f, b1 = bias ? bias[o + 1] : 0.f;
                    u0 += b0; u1 += b1; u2 += b0; u3 += b1;
                    if (act) {
                        u0 = u0 > 0.f ? u0 : 0.2f * u0;
                        u1 = u1 > 0.f ? u1 : 0.2f * u1;
                        u2 = u2 > 0.f ? u2 : 0.2f * u2;
                        u3 = u3 > 0.f ? u3 : 0.2f * u3;
                    }
                } else {
                    float xc0 = xxb[o], xc1 = xxb[o + 1];
                    u0 = xrA - 2.f * u0 + xc0; u1 = xrA - 2.f * u1 + xc1;
                    u2 = xrB - 2.f * u2 + xc0; u3 = xrB - 2.f * u3 + xc1;
                }
                *(float2*)(outb + (size_t)mA * ldo + o)       = make_float2(u0, u1);
                *(float2*)(outb + (size_t)(mA + 8) * ldo + o) = make_float2(u2, u3);
            }
        }
    }
}

// =================== warp-per-row top-K, float4 scan ===================
__global__ void topk_warp(const float* __restrict__ d2, int* __restrict__ idx) {
    __shared__ float sk[8][32 * KNN];
    __shared__ int   si[8][32 * KNN];
    int w = threadIdx.x >> 5, lane = threadIdx.x & 31;
    int row = blockIdx.x * 8 + w;
    const float* r = d2 + (size_t)row * NN;
    float key[KNN]; int ki[KNN];
#pragma unroll
    for (int j = 0; j < KNN; ++j) { key[j] = FLT_MAX; ki[j] = 0; }

#pragma unroll 2
    for (int j = 0; j < 16; ++j) {
        int e0 = 4 * (j * 32 + lane);
        float4 v4 = *(const float4*)(r + e0);
        float vmin = fminf(fminf(v4.x, v4.y), fminf(v4.z, v4.w));
        if (vmin < key[KNN - 1]) {
            float vals[4] = {v4.x, v4.y, v4.z, v4.w};
#pragma unroll
            for (int q = 0; q < 4; ++q) {
                float cv = vals[q];
                if (cv < key[KNN - 1]) {
                    int ci = e0 + q;
#pragma unroll
                    for (int jj = 0; jj < KNN; ++jj) {
                        if (cv < key[jj]) {
                            float tv = key[jj]; key[jj] = cv; cv = tv;
                            int ti = ki[jj]; ki[jj] = ci; ci = ti;
                        }
                    }
                }
            }
        }
    }
#pragma unroll
    for (int j = 0; j < KNN; ++j) {
        sk[w][lane * KNN + j] = key[j];
        si[w][lane * KNN + j] = ki[j];
    }
    __syncwarp();
    int h = 0;
    float hv = key[0]; int hi = ki[0];
    for (int k = 0; k < KNN; ++k) {
        unsigned ub = __float_as_uint(hv);
        ub = (ub & 0x80000000u) ? ~ub : (ub | 0x80000000u);
        unsigned long long pk = ((unsigned long long)ub << 32) | (unsigned)lane;
#pragma unroll
        for (int off = 16; off; off >>= 1) {
            unsigned long long o = __shfl_xor_sync(0xffffffffu, pk, off);
            pk = (o < pk) ? o : pk;
        }
        int src = (int)(pk & 31u);
        int widx = __shfl_sync(0xffffffffu, hi, src);
        if (lane == 0) idx[(size_t)row * KNN + k] = widx;
        if (lane == src) {
            ++h;
            hv = (h < KNN) ? sk[w][lane * KNN + h] : FLT_MAX;
            hi = (h < KNN) ? si[w][lane * KNN + h] : 0;
        }
    }
}

// =================== small kernels ===================
__global__ void xx_kernel(const float* __restrict__ X, int ldx, int C,
                          float* __restrict__ xx) {
    int i = blockIdx.x * blockDim.x + threadIdx.x;
    if (i >= BB * NN) return;
    const float* p = X + (size_t)i * ldx;
    float s = 0.f;
    for (int c = 0; c < C; ++c) { float v = p[c]; s += v * v; }
    xx[i] = s;
}

// combined yc buffer: y at cols [0,O), c at cols [O,2O), row stride 2O; float4/thread
__global__ void edgemax4(const float* __restrict__ yc, const int* __restrict__ idx,
                         float* __restrict__ out, int O, int ldo) {
    __shared__ int sid[KNN];
    int b = blockIdx.y, n = blockIdx.x;
    int t = threadIdx.x;                      // 0 .. O/4-1
    for (int i = t; i < KNN; i += blockDim.x)
        sid[i] = idx[((size_t)b * NN + n) * KNN + i];
    __syncthreads();
    size_t mbase = (size_t)b * NN;
    int ld2 = 2 * O;
    const float* prow = yc + (mbase + n) * ld2 + 4 * t;
    float4 ycn = *(const float4*)prow;
    float4 ccn = *(const float4*)(prow + O);
    float4 m = make_float4(-FLT_MAX, -FLT_MAX, -FLT_MAX, -FLT_MAX);
#pragma unroll
    for (int k = 0; k < KNN; ++k) {
        float4 yn = *(const float4*)(yc + (mbase + sid[k]) * ld2 + 4 * t);
        float v0 = yn.x - ycn.x + ccn.x;
        float v1 = yn.y - ycn.y + ccn.y;
        float v2 = yn.z - ycn.z + ccn.z;
        float v3 = yn.w - ycn.w + ccn.w;
        v0 = v0 > 0.f ? v0 : 0.2f * v0;
        v1 = v1 > 0.f ? v1 : 0.2f * v1;
        v2 = v2 > 0.f ? v2 : 0.2f * v2;
        v3 = v3 > 0.f ? v3 : 0.2f * v3;
        m.x = fmaxf(m.x, v0); m.y = fmaxf(m.y, v1);
        m.z = fmaxf(m.z, v2); m.w = fmaxf(m.w, v3);
    }
    *(float4*)(out + (mbase + n) * ldo + 4 * t) = m;
}

__global__ void maxpool(const float* __restrict__ tmp, float* __restrict__ out) {
    int b = blockIdx.y;
    int f = blockIdx.x * blockDim.x + threadIdx.x;
    const float* p = tmp + (size_t)b * NN * 1024 + f;
    float m = -FLT_MAX;
    for (int n = 0; n < NN; ++n) m = fmaxf(m, p[(size_t)n * 1024]);
    out[b * 1024 + f] = m;
}

// =================== launch ===================
extern "C" void kernel_launch(void* const* d_in, const int* in_sizes, int n_in,
                              void* d_out, int out_size) {
    const float* x     = (const float*)d_in[0];
    const float* Wl[4] = {(const float*)d_in[1], (const float*)d_in[3],
                          (const float*)d_in[5], (const float*)d_in[7]};
    const float* bl[4] = {(const float*)d_in[2], (const float*)d_in[4],
                          (const float*)d_in[6], (const float*)d_in[8]};
    const float* Wf = (const float*)d_in[9];
    const float* bf = (const float*)d_in[10];
    float* out = (float*)d_out;

    float *p_d2, *p_xx, *p_yc, *p_hcat, *p_tmp, *p_bias2;
    __nv_bfloat16 *p_a3, *p_b3, *p_bf3, *p_w3;
    int* p_idx;
    cudaGetSymbolAddress((void**)&p_d2,    g_d2);
    cudaGetSymbolAddress((void**)&p_xx,    g_xx);
    cudaGetSymbolAddress((void**)&p_idx,   g_idx);
    cudaGetSymbolAddress((void**)&p_yc,    g_yc);
    cudaGetSymbolAddress((void**)&p_hcat,  g_hcat);
    cudaGetSymbolAddress((void**)&p_tmp,   g_tmp);
    cudaGetSymbolAddress((void**)&p_bias2, g_bias2);
    cudaGetSymbolAddress((void**)&p_a3,    g_a3);
    cudaGetSymbolAddress((void**)&p_b3,    g_b3);
    cudaGetSymbolAddress((void**)&p_bf3,   g_bf3);
    cudaGetSymbolAddress((void**)&p_w3,    g_w3);

    cudaFuncSetAttribute(mma_gemm, cudaFuncAttributeMaxDynamicSharedMemorySize,
                         MMA_SMEM);

    const int Cs[4]  = {3, 64, 64, 128};
    const int Os[4]  = {64, 64, 128, 256};
    const int off[4] = {0, 64, 128, 256};

    const float* Xin = x;
    int ldx = 3;
    for (int l = 0; l < 4; ++l) {
        int C = Cs[l], O = Os[l];
        int K3 = ((3 * C + 63) / 64) * 64;     // 64, 192, 192, 384

        xx_kernel<<<(BB * NN + 255) / 256, 256>>>(Xin, ldx, C, p_xx);
        convA_kernel<<<dim3((K3 + 255) / 256, BB * NN), 256>>>(Xin, ldx, C, p_a3, K3);
        convB_kernel<<<dim3((K3 + 255) / 256, BB * NN), 256>>>(Xin, ldx, C, p_b3, K3);
        // pairwise d2
        mma_gemm<<<dim3(16, 16, BB), 256, MMA_SMEM>>>(
            p_a3, K3, (size_t)NN * K3, p_b3, K3, (size_t)NN * K3,
            NN, K3, p_d2, NN, (size_t)NN * NN, nullptr, 0, 1, p_xx, NN);
        topk_warp<<<(BB * NN) / 8, 256>>>(p_d2, p_idx);
        // combined yc = X * [Wy|Wc]^T + [0|b]
        convB_kernel<<<dim3((K3 + 255) / 256, O), 256>>>(Wl[l], 2 * C, C, p_w3, K3);
        convB_kernel<<<dim3((K3 + 255) / 256, O), 256>>>(Wl[l] + C, 2 * C, C,
                                                         p_w3 + (size_t)O * K3, K3);
        biascat<<<1, 512>>>(bl[l], p_bias2, O);
        mma_gemm<<<dim3((2 * O + 127) / 128, (BB * NN) / 128, 1), 256, MMA_SMEM>>>(
            p_a3, K3, 0, p_w3, K3, 0, 2 * O, K3,
            p_yc, 2 * O, 0, p_bias2, 0, 0, nullptr, 0);
        edgemax4<<<dim3(NN, BB), O / 4>>>(p_yc, p_idx, p_hcat + off[l], O, 512);
        Xin = p_hcat + off[l];
        ldx = 512;
    }
    // final 512 -> 1024 linear + leaky, then max over N
    convA_kernel<<<dim3(1536 / 256, BB * NN), 256>>>(p_hcat, 512, 512, p_a3, 1536);
    convB_kernel<<<dim3(1536 / 256, 1024), 256>>>(Wf, 512, 512, p_bf3, 1536);
    mma_gemm<<<dim3(1024 / 128, (BB * NN) / 128, 1), 256, MMA_SMEM>>>(
        p_a3, 1536, 0, p_bf3, 1536, 0, 1024, 1536,
        p_tmp, 1024, 0, bf, 1, 0, nullptr, 0);
    maxpool<<<dim3(1024 / 256, BB), 256>>>(p_tmp, out);
}